// round 1
// baseline (speedup 1.0000x reference)
#include <cuda_runtime.h>

// Problem constants (fixed by the dataset)
#define D_   64     // node feature dim
#define H_   64     // hidden dim
#define EF_  16     // edge feature dim
#define FK   145    // 2*D + 1 + EF
#define TE   64     // edges per tile
#define FPAD 148    // padded row stride of F tile (row-major)
#define MPAD 68     // padded row stride of M / T tiles
#define TN   64     // nodes per tile
#define ZK   128    // D + H
#define ZPAD 132    // padded row stride of Z tile
#define NMAX 50000

// Scratch for scatter-sum aggregation (device global: no allocations allowed)
__device__ float g_hneigh[(size_t)NMAX * H_];

__device__ __forceinline__ float silu_f(float x) {
    // x * sigmoid(x); fast exp/div intrinsics (rel err ~1e-6, far under 1e-3 budget)
    return __fdividef(x, 1.0f + __expf(-x));
}

__global__ void zero_hneigh(int n4) {
    float4 z = make_float4(0.f, 0.f, 0.f, 0.f);
    for (int i = blockIdx.x * blockDim.x + threadIdx.x; i < n4;
         i += gridDim.x * blockDim.x)
        reinterpret_cast<float4*>(g_hneigh)[i] = z;
}

extern __shared__ float smem_dyn[];

// ---------------------------------------------------------------------------
// Edge kernel: msg = silu(silu(F @ W_e1 + b1) @ W_e2 + b2); scatter-add to dst
// Persistent blocks, 64-edge tiles, 256 threads as 16x16, 4x4 frag per thread.
// ---------------------------------------------------------------------------
__global__ __launch_bounds__(256, 2) void edge_kernel(
    const float* __restrict__ node_feat, const float* __restrict__ coord,
    const float* __restrict__ edge_feat, const int* __restrict__ src,
    const int* __restrict__ dst, const float* __restrict__ W_e1,
    const float* __restrict__ b_e1, const float* __restrict__ W_e2,
    const float* __restrict__ b_e2, int E)
{
    float* W1s = smem_dyn;                 // [FK][64]   9280 f
    float* W2s = W1s + FK * H_;            // [64][64]   4096 f
    float* b1s = W2s + H_ * H_;            // 64 f
    float* b2s = b1s + H_;                 // 64 f
    float* Fs  = b2s + H_;                 // [TE][FPAD] 9472 f (row-major)
    float* Ms  = Fs + TE * FPAD;           // [TE][MPAD] 4352 f
    int*   sSrc = (int*)(Ms + TE * MPAD);  // 64 i
    int*   sDst = sSrc + TE;               // 64 i

    const int tid = threadIdx.x;
    const int tx  = tid & 15;              // output-column group (4*tx .. 4*tx+3)
    const int ty  = tid >> 4;              // edge-row group (4*ty .. 4*ty+3)

    // Load weights once per (persistent) block
    for (int i = tid; i < FK * H_; i += 256) W1s[i] = W_e1[i];
    for (int i = tid; i < H_ * H_; i += 256) W2s[i] = W_e2[i];
    if (tid < H_) { b1s[tid] = b_e1[tid]; b2s[tid] = b_e2[tid]; }

    const int ntiles = (E + TE - 1) / TE;
    for (int tile = blockIdx.x; tile < ntiles; tile += gridDim.x) {
        const int e0 = tile * TE;
        __syncthreads();   // previous iteration's shared reads complete

        // Phase A: indices + radial
        if (tid < TE) {
            int e = e0 + tid;
            int s = 0, d = 0;
            float radial = 0.f;
            if (e < E) {
                s = src[e]; d = dst[e];
                float dx = coord[3 * s + 0] - coord[3 * d + 0];
                float dy = coord[3 * s + 1] - coord[3 * d + 1];
                float dz = coord[3 * s + 2] - coord[3 * d + 2];
                radial = dx * dx + dy * dy + dz * dz;
            }
            sSrc[tid] = s; sDst[tid] = d;
            Fs[tid * FPAD + 2 * D_] = radial;
        }
        __syncthreads();

        // Phase B: gather node features (coalesced 256B rows) + edge features
        #pragma unroll
        for (int it = 0; it < 16; it++) {
            int idx = it * 256 + tid;
            int r = idx >> 6, k = idx & 63;
            int s = sSrc[r], d = sDst[r];
            Fs[r * FPAD + k]       = node_feat[s * D_ + k];
            Fs[r * FPAD + D_ + k]  = node_feat[d * D_ + k];
        }
        #pragma unroll
        for (int it = 0; it < 4; it++) {
            int idx = it * 256 + tid;
            int r = idx >> 4, j = idx & 15;
            int e = e0 + r;
            Fs[r * FPAD + 2 * D_ + 1 + j] = (e < E) ? edge_feat[e * EF_ + j] : 0.f;
        }
        __syncthreads();

        // Stage 1: M = silu(F @ W_e1 + b1)
        float acc[4][4];
        {
            const float4 bv = *reinterpret_cast<const float4*>(&b1s[tx * 4]);
            #pragma unroll
            for (int i = 0; i < 4; i++) {
                acc[i][0] = bv.x; acc[i][1] = bv.y; acc[i][2] = bv.z; acc[i][3] = bv.w;
            }
        }
        const float* fb = &Fs[(ty * 4) * FPAD];
        #pragma unroll 5
        for (int k = 0; k < FK; k++) {
            const float4 w = *reinterpret_cast<const float4*>(&W1s[k * H_ + tx * 4]);
            #pragma unroll
            for (int i = 0; i < 4; i++) {
                float f = fb[i * FPAD + k];   // broadcast LDS
                acc[i][0] += f * w.x; acc[i][1] += f * w.y;
                acc[i][2] += f * w.z; acc[i][3] += f * w.w;
            }
        }
        {
            float* mrow = &Ms[(ty * 4) * MPAD + tx * 4];
            #pragma unroll
            for (int i = 0; i < 4; i++)
                #pragma unroll
                for (int j = 0; j < 4; j++)
                    mrow[i * MPAD + j] = silu_f(acc[i][j]);
        }
        __syncthreads();

        // Stage 2: msg = silu(M @ W_e2 + b2)
        float acc2[4][4];
        {
            const float4 bv = *reinterpret_cast<const float4*>(&b2s[tx * 4]);
            #pragma unroll
            for (int i = 0; i < 4; i++) {
                acc2[i][0] = bv.x; acc2[i][1] = bv.y; acc2[i][2] = bv.z; acc2[i][3] = bv.w;
            }
        }
        const float* mb = &Ms[(ty * 4) * MPAD];
        #pragma unroll 8
        for (int k = 0; k < H_; k++) {
            const float4 w = *reinterpret_cast<const float4*>(&W2s[k * H_ + tx * 4]);
            #pragma unroll
            for (int i = 0; i < 4; i++) {
                float m = mb[i * MPAD + k];
                acc2[i][0] += m * w.x; acc2[i][1] += m * w.y;
                acc2[i][2] += m * w.z; acc2[i][3] += m * w.w;
            }
        }

        // Scatter: vectorized global reduction (no return value -> REDG)
        #pragma unroll
        for (int i = 0; i < 4; i++) {
            int r = ty * 4 + i;
            if (e0 + r < E) {
                float v0 = silu_f(acc2[i][0]);
                float v1 = silu_f(acc2[i][1]);
                float v2 = silu_f(acc2[i][2]);
                float v3 = silu_f(acc2[i][3]);
                float* p = &g_hneigh[(size_t)sDst[r] * H_ + tx * 4];
                asm volatile("red.global.add.v4.f32 [%0], {%1,%2,%3,%4};"
                             :: "l"(p), "f"(v0), "f"(v1), "f"(v2), "f"(v3)
                             : "memory");
            }
        }
    }
}

// ---------------------------------------------------------------------------
// Node kernel: out = silu([h, h_neigh] @ W_n1 + b1) @ W_n2 + b2
// ---------------------------------------------------------------------------
__global__ __launch_bounds__(256, 2) void node_kernel(
    const float* __restrict__ node_feat,
    const float* __restrict__ W_n1, const float* __restrict__ b_n1,
    const float* __restrict__ W_n2, const float* __restrict__ b_n2,
    float* __restrict__ out, int N)
{
    float* W1s = smem_dyn;                 // [128][64]  8192 f
    float* W2s = W1s + ZK * H_;            // [64][64]   4096 f
    float* b1s = W2s + H_ * D_;            // 64 f
    float* b2s = b1s + H_;                 // 64 f
    float* Zs  = b2s + D_;                 // [TN][ZPAD] 8448 f
    float* Ts  = Zs + TN * ZPAD;           // [TN][MPAD] 4352 f

    const int tid = threadIdx.x;
    const int tx  = tid & 15;
    const int ty  = tid >> 4;

    for (int i = tid; i < ZK * H_; i += 256) W1s[i] = W_n1[i];
    for (int i = tid; i < H_ * D_; i += 256) W2s[i] = W_n2[i];
    if (tid < H_) b1s[tid] = b_n1[tid];
    if (tid < D_) b2s[tid] = b_n2[tid];

    const int ntiles = (N + TN - 1) / TN;
    for (int tile = blockIdx.x; tile < ntiles; tile += gridDim.x) {
        const int n0 = tile * TN;
        __syncthreads();

        // Fill Z = [node_feat | h_neigh]
        #pragma unroll
        for (int it = 0; it < 32; it++) {
            int idx = it * 256 + tid;
            int r = idx >> 7, k = idx & 127;
            int n = n0 + r;
            float v = 0.f;
            if (n < N)
                v = (k < D_) ? node_feat[n * D_ + k]
                             : g_hneigh[(size_t)n * H_ + (k - D_)];
            Zs[r * ZPAD + k] = v;
        }
        __syncthreads();

        // Stage 1: T = silu(Z @ W_n1 + b1)
        float acc[4][4];
        {
            const float4 bv = *reinterpret_cast<const float4*>(&b1s[tx * 4]);
            #pragma unroll
            for (int i = 0; i < 4; i++) {
                acc[i][0] = bv.x; acc[i][1] = bv.y; acc[i][2] = bv.z; acc[i][3] = bv.w;
            }
        }
        const float* zb = &Zs[(ty * 4) * ZPAD];
        #pragma unroll 8
        for (int k = 0; k < ZK; k++) {
            const float4 w = *reinterpret_cast<const float4*>(&W1s[k * H_ + tx * 4]);
            #pragma unroll
            for (int i = 0; i < 4; i++) {
                float z = zb[i * ZPAD + k];
                acc[i][0] += z * w.x; acc[i][1] += z * w.y;
                acc[i][2] += z * w.z; acc[i][3] += z * w.w;
            }
        }
        {
            float* trow = &Ts[(ty * 4) * MPAD + tx * 4];
            #pragma unroll
            for (int i = 0; i < 4; i++)
                #pragma unroll
                for (int j = 0; j < 4; j++)
                    trow[i * MPAD + j] = silu_f(acc[i][j]);
        }
        __syncthreads();

        // Stage 2: out = T @ W_n2 + b2   (no activation)
        float acc2[4][4];
        {
            const float4 bv = *reinterpret_cast<const float4*>(&b2s[tx * 4]);
            #pragma unroll
            for (int i = 0; i < 4; i++) {
                acc2[i][0] = bv.x; acc2[i][1] = bv.y; acc2[i][2] = bv.z; acc2[i][3] = bv.w;
            }
        }
        const float* tb = &Ts[(ty * 4) * MPAD];
        #pragma unroll 8
        for (int k = 0; k < H_; k++) {
            const float4 w = *reinterpret_cast<const float4*>(&W2s[k * D_ + tx * 4]);
            #pragma unroll
            for (int i = 0; i < 4; i++) {
                float t = tb[i * MPAD + k];
                acc2[i][0] += t * w.x; acc2[i][1] += t * w.y;
                acc2[i][2] += t * w.z; acc2[i][3] += t * w.w;
            }
        }
        #pragma unroll
        for (int i = 0; i < 4; i++) {
            int n = n0 + ty * 4 + i;
            if (n < N) {
                float4 v = make_float4(acc2[i][0], acc2[i][1], acc2[i][2], acc2[i][3]);
                *reinterpret_cast<float4*>(&out[(size_t)n * D_ + tx * 4]) = v;
            }
        }
    }
}

extern "C" void kernel_launch(void* const* d_in, const int* in_sizes, int n_in,
                              void* d_out, int out_size)
{
    const float* node_feat = (const float*)d_in[0];
    const float* coord     = (const float*)d_in[1];
    const float* edge_feat = (const float*)d_in[2];
    const int*   src       = (const int*)d_in[3];
    const int*   dst       = (const int*)d_in[4];
    const float* W_e1      = (const float*)d_in[5];
    const float* b_e1      = (const float*)d_in[6];
    const float* W_e2      = (const float*)d_in[7];
    const float* b_e2      = (const float*)d_in[8];
    const float* W_n1      = (const float*)d_in[9];
    const float* b_n1      = (const float*)d_in[10];
    const float* W_n2      = (const float*)d_in[11];
    const float* b_n2      = (const float*)d_in[12];
    float* out = (float*)d_out;

    const int N = in_sizes[0] / D_;
    const int E = in_sizes[3];

    const size_t smemE =
        (size_t)(FK * H_ + H_ * H_ + 2 * H_ + TE * FPAD + TE * MPAD) * 4 +
        2 * TE * 4;
    const size_t smemN =
        (size_t)(ZK * H_ + H_ * D_ + H_ + D_ + TN * ZPAD + TN * MPAD) * 4;

    cudaFuncSetAttribute(edge_kernel,
                         cudaFuncAttributeMaxDynamicSharedMemorySize, (int)smemE);
    cudaFuncSetAttribute(node_kernel,
                         cudaFuncAttributeMaxDynamicSharedMemorySize, (int)smemN);

    zero_hneigh<<<512, 256>>>(N * H_ / 4);
    edge_kernel<<<296, 256, smemE>>>(node_feat, coord, edge_feat, src, dst,
                                     W_e1, b_e1, W_e2, b_e2, E);
    node_kernel<<<296, 256, smemN>>>(node_feat, W_n1, b_n1, W_n2, b_n2, out, N);
}